// round 2
// baseline (speedup 1.0000x reference)
#include <cuda_runtime.h>

#define NEGF  (-1e30f)
#define EPSF  (1e-7f)
#define LN2F  (0.6931471805599453f)
#define PF    8

__device__ __forceinline__ float ex2f_(float x) {
    float r; asm("ex2.approx.ftz.f32 %0, %1;" : "=f"(r) : "f"(x)); return r;
}
__device__ __forceinline__ float lg2f_(float x) {
    float r; asm("lg2.approx.ftz.f32 %0, %1;" : "=f"(r) : "f"(x)); return r;
}

// One CTA per batch row. Thread s owns extended-label state s (s < S = 2L+1).
// Alpha recursion runs in log2 space; alpha ping-pongs through shared memory
// with one __syncthreads per time step. Emission probs are gathered straight
// from y_pred (only the <=65 needed classes) with a depth-PF register
// prefetch pipeline to hide DRAM latency.
__global__ __launch_bounds__(256)
void CTCLayer_5669356831169_kernel(const int* __restrict__ y_true,
                                   const float* __restrict__ y_pred,
                                   float* __restrict__ out,
                                   int T, int C, int L)
{
    extern __shared__ float shraw[];
    const int b  = blockIdx.x;
    const int s  = threadIdx.x;
    const int nt = blockDim.x;

    // Layout: [pad2 | buf0(nt) | pad2 | buf1(nt) | ll]
    float* buf0  = shraw + 2;
    float* buf1  = shraw + 2 + nt + 2;
    int*   sh_ll = (int*)(shraw + 2 * nt + 4);

    const int  blank = C - 1;
    const int  S     = 2 * L + 1;
    const int* yt    = y_true + (size_t)b * L;

    // label length = count(y_true != -1)
    if (s == 0) {
        int ll = 0;
        #pragma unroll 8
        for (int i = 0; i < L; ++i) ll += (yt[i] != -1);
        *sh_ll = ll;
    }
    __syncthreads();
    const int ll = *sh_ll;

    // this state's class in the extended sequence (blank, l1, blank, l2, ...)
    int cls = blank;
    if ((s & 1) && s < S) {
        int raw = yt[(s - 1) >> 1];
        cls = (raw < 0) ? blank : raw;
    }
    const bool valid  = (s < S) && (s < 2 * ll + 1);
    const bool has1   = (s >= 1);
    bool allow2 = false;
    if (s >= 2 && (s & 1) && s < S) {
        int raw2 = yt[(s - 3) >> 1];
        int cls2 = (raw2 < 0) ? blank : raw2;
        allow2 = (cls != blank) && (cls != cls2);
    }

    const float* yp = y_pred + (size_t)b * T * C + cls;

    // t = 0 init: alpha0[s] = (s < 2 && valid) ? log2(p + eps) : NEG
    float my;
    {
        bool init_ok = valid && (s < 2);
        float p = init_ok ? __ldg(yp) : 1.0f;
        my = init_ok ? lg2f_(p + EPSF) : NEGF;
    }
    float* rd = buf0;
    float* wr = buf1;
    rd[s] = my;
    __syncthreads();

    // Prefetch raw probs for steps t = 1..PF
    float cur[PF], nxt[PF];
    #pragma unroll
    for (int u = 0; u < PF; ++u) {
        int t0 = 1 + u;
        cur[u] = (valid && t0 < T) ? __ldg(yp + (size_t)t0 * C) : 1.0f;
    }

    int t = 1;
    // Full blocks of PF steps; loads for block k+1 issued before computing block k.
    for (; t + PF <= T; t += PF) {
        #pragma unroll
        for (int u = 0; u < PF; ++u) {
            int tn = t + PF + u;
            nxt[u] = (valid && tn < T) ? __ldg(yp + (size_t)tn * C) : 1.0f;
        }
        #pragma unroll
        for (int u = 0; u < PF; ++u) {
            float a  = my;
            float bb = has1   ? rd[s - 1] : NEGF;
            float cc = allow2 ? rd[s - 2] : NEGF;
            float m   = fmaxf(a, fmaxf(bb, cc));
            float sum = ex2f_(a - m) + ex2f_(bb - m) + ex2f_(cc - m);
            float e2  = lg2f_(cur[u] + EPSF);
            float nv  = valid ? (e2 + m + lg2f_(sum)) : NEGF;
            wr[s] = nv;
            my = nv;
            __syncthreads();
            float* tmp = rd; rd = wr; wr = tmp;
        }
        #pragma unroll
        for (int u = 0; u < PF; ++u) cur[u] = nxt[u];
    }
    // Remainder (< PF steps), statically unrolled so cur[] stays in registers.
    #pragma unroll
    for (int u = 0; u < PF - 1; ++u) {
        if (t + u < T) {
            float a  = my;
            float bb = has1   ? rd[s - 1] : NEGF;
            float cc = allow2 ? rd[s - 2] : NEGF;
            float m   = fmaxf(a, fmaxf(bb, cc));
            float sum = ex2f_(a - m) + ex2f_(bb - m) + ex2f_(cc - m);
            float e2  = lg2f_(cur[u] + EPSF);
            float nv  = valid ? (e2 + m + lg2f_(sum)) : NEGF;
            wr[s] = nv;
            my = nv;
            __syncthreads();
            float* tmp = rd; rd = wr; wr = tmp;
        }
    }

    // rd holds alpha at t = T-1. loss = -logaddexp(a[2ll], a[2ll-1]) (ln space)
    if (s == 0) {
        float a1 = rd[2 * ll];
        float a0 = (ll > 0) ? rd[2 * ll - 1] : NEGF;
        float m  = fmaxf(a1, a0);
        float r  = m + lg2f_(ex2f_(a1 - m) + ex2f_(a0 - m));
        out[b] = -LN2F * r;
    }
}

extern "C" void kernel_launch(void* const* d_in, const int* in_sizes, int n_in,
                              void* d_out, int out_size) {
    const int*   y_true = (const int*)d_in[0];
    const float* y_pred = (const float*)d_in[1];
    float*       out    = (float*)d_out;

    const int B = out_size;                 // output is [B, 1]
    const int L = in_sizes[0] / B;          // 64
    const int C = 1024;                     // classes (blank = C-1)
    const int T = in_sizes[1] / (B * C);    // 512

    const int S  = 2 * L + 1;               // 129
    const int nt = ((S + 31) / 32) * 32;    // 160 threads
    size_t smem = (size_t)(2 * nt + 8) * sizeof(float);

    CTCLayer_5669356831169_kernel<<<B, nt, smem>>>(y_true, y_pred, out, T, C, L);
}

// round 3
// speedup vs baseline: 1.1171x; 1.1171x over previous
#include <cuda_runtime.h>

#define NEGF  (-1e30f)
#define EPSF  (1e-7f)
#define LN2F  (0.6931471805599453f)
#define K_BLK 8          // time steps per producer/consumer block
#define RING  16         // 2 * K_BLK ring slots
#define NPROD 160        // producer threads
#define MAXQ  4          // max gathers per producer thread per block

__device__ __forceinline__ float ex2f_(float x) {
    float r; asm("ex2.approx.ftz.f32 %0, %1;" : "=f"(r) : "f"(x)); return r;
}
__device__ __forceinline__ float lg2f_(float x) {
    float r; asm("lg2.approx.ftz.f32 %0, %1;" : "=f"(r) : "f"(x)); return r;
}
__device__ __forceinline__ void barDP(int cnt) {
    asm volatile("bar.sync 1, %0;" :: "r"(cnt) : "memory");
}

// One CTA per batch row b. Threads [0, nt_dp): DP over extended states s
// (alpha recursion in log2 space, named barrier per step). Threads
// [nt_dp, nt_dp+NPROD): producers that gather the <=L+1 unique class
// probabilities per time step straight from y_pred, compute log2(p+eps),
// and stream them into a shared ring buffer, pipelined 3 blocks ahead.
__global__ __launch_bounds__(320)
void CTCLayer_5669356831169_kernel(const int* __restrict__ y_true,
                                   const float* __restrict__ y_pred,
                                   float* __restrict__ out,
                                   int T, int C, int L, int nt_dp)
{
    extern __shared__ float sh[];
    const int b     = blockIdx.x;
    const int tid   = threadIdx.x;
    const int blank = C - 1;
    const int S     = 2 * L + 1;
    const int ncls  = L + 1;          // unique classes per row: labels + blank
    const int slotw = ncls + 1;       // ring slot stride (floats)

    // shared layout (floats): classes[ncls] | ring[RING*slotw] | pad2 a0[nt_dp] | pad2 a1[nt_dp] | ll
    int*   classes = (int*)sh;
    float* ring    = sh + ncls;
    float* abuf0   = ring + RING * slotw + 2;
    float* abuf1   = abuf0 + nt_dp + 2;
    int*   sh_ll   = (int*)(abuf1 + nt_dp);

    const int* yt = y_true + (size_t)b * L;

    // init class table + label length
    for (int j = tid; j < ncls; j += blockDim.x) {
        int c = blank;
        if (j < L) { int raw = yt[j]; c = (raw < 0) ? blank : raw; }
        classes[j] = c;
    }
    if (tid == 0) {
        int ll = 0;
        for (int i = 0; i < L; ++i) ll += (yt[i] != -1);
        *sh_ll = ll;
    }
    __syncthreads();

    const int NB  = (T + K_BLK - 1) / K_BLK;
    const int NB3 = ((NB + 2) / 3) * 3;       // producer loop is 3-phase

    if (tid >= nt_dp) {
        // ------------------- producer -------------------
        const int pid = tid - nt_dp;
        const float* yrow = y_pred + (size_t)b * T * C;
        const int LPB = K_BLK * ncls;          // gathers per block (520)

        int  uu[MAXQ], jj[MAXQ], cc[MAXQ];
        bool ok[MAXQ];
        #pragma unroll
        for (int i = 0; i < MAXQ; ++i) {
            int q = pid + NPROD * i;
            ok[i] = (q < LPB);
            int u = ok[i] ? q / ncls : 0;
            int j = ok[i] ? q % ncls : 0;
            uu[i] = u; jj[i] = j; cc[i] = classes[j];
        }

        float bv0[MAXQ], bv1[MAXQ], bv2[MAXQ];

        #define PLDG(buf, m) do {                                             \
            int _t0 = (m) * K_BLK;                                            \
            _Pragma("unroll")                                                 \
            for (int i = 0; i < MAXQ; ++i) {                                  \
                int _t = _t0 + uu[i];                                         \
                buf[i] = (ok[i] && _t < T)                                    \
                    ? __ldg(yrow + (size_t)_t * C + cc[i]) : 1.0f;            \
            } } while (0)

        #define PSTS(buf, m) do {                                             \
            int _t0 = (m) * K_BLK;                                            \
            _Pragma("unroll")                                                 \
            for (int i = 0; i < MAXQ; ++i) {                                  \
                int _t = _t0 + uu[i];                                         \
                if (ok[i] && _t < T)                                          \
                    ring[(_t % RING) * slotw + jj[i]] = lg2f_(buf[i] + EPSF); \
            } } while (0)

        // prologue: blocks 0,1,2 into bv0,bv1,bv2; store block 0
        PLDG(bv0, 0); PLDG(bv1, 1); PLDG(bv2, 2);
        PSTS(bv0, 0);
        __syncthreads();

        #define PITER(k, stsbuf, ldgbuf) do {                                 \
            int _m = (k) + 1;                                                 \
            if (_m < NB) PSTS(stsbuf, _m);                                    \
            int _ml = (k) + 3;                                                \
            if (_ml < NB) PLDG(ldgbuf, _ml);                                  \
            __syncthreads(); } while (0)

        for (int k = 0; k < NB3; k += 3) {
            PITER(k,     bv1, bv0);   // STS block k+1 (bv1), LDG block k+3 -> bv0
            PITER(k + 1, bv2, bv1);
            PITER(k + 2, bv0, bv2);
        }
        #undef PITER
        #undef PSTS
        #undef PLDG
    } else {
        // ------------------- DP consumer -------------------
        const int s  = tid;
        const int ll = *sh_ll;

        const int  col    = (s & 1) ? ((s - 1) >> 1) : (ncls - 1);  // blank at ncls-1
        const bool valid  = (s < S) && (s < 2 * ll + 1);
        const bool has1   = (s >= 1);
        bool allow2 = false;
        if (s >= 2 && (s & 1) && s < S) {
            int c1 = classes[(s - 1) >> 1];
            int c2 = classes[(s - 3) >> 1];
            allow2 = (c1 != blank) && (c1 != c2);
        }

        float* rd = abuf0;
        float* wr = abuf1;
        float  my = NEGF;

        __syncthreads();   // matches producer prologue sync

        for (int k = 0; k < NB3; ++k) {
            #pragma unroll
            for (int u = 0; u < K_BLK; ++u) {
                int t = k * K_BLK + u;
                if (t < T) {
                    float le = ring[(t % RING) * slotw + col];  // log2(p+eps)
                    float nv;
                    if (t == 0) {
                        nv = (valid && s < 2) ? le : NEGF;
                    } else {
                        float bb  = has1   ? rd[s - 1] : NEGF;
                        float cc2 = allow2 ? rd[s - 2] : NEGF;
                        float m0  = fmaxf(my, fmaxf(bb, cc2));
                        float sum = ex2f_(my - m0) + ex2f_(bb - m0) + ex2f_(cc2 - m0);
                        nv = valid ? (le + m0 + lg2f_(sum)) : NEGF;
                    }
                    wr[s] = nv;
                    my = nv;
                }
                barDP(nt_dp);
                if (t < T) { float* tmp = rd; rd = wr; wr = tmp; }
            }
            __syncthreads();   // block-boundary handoff with producers
        }

        // rd holds alpha at t = T-1 (log2). loss = -ln(2) * log2-addexp
        if (s == 0) {
            float a1 = rd[2 * ll];
            float a0 = (ll > 0) ? rd[2 * ll - 1] : NEGF;
            float m  = fmaxf(a1, a0);
            float r  = m + lg2f_(ex2f_(a1 - m) + ex2f_(a0 - m));
            out[b] = -LN2F * r;
        }
    }
}

extern "C" void kernel_launch(void* const* d_in, const int* in_sizes, int n_in,
                              void* d_out, int out_size) {
    const int*   y_true = (const int*)d_in[0];
    const float* y_pred = (const float*)d_in[1];
    float*       out    = (float*)d_out;

    const int B = out_size;                 // output is [B, 1]
    const int L = in_sizes[0] / B;          // 64
    const int C = 1024;                     // classes (blank = C-1)
    const int T = in_sizes[1] / (B * C);    // 512

    const int S     = 2 * L + 1;                    // 129
    const int nt_dp = ((S + 31) / 32) * 32;         // 160
    const int nt    = nt_dp + NPROD;                // 320

    const int ncls  = L + 1;
    const int slotw = ncls + 1;
    size_t smem = (size_t)(ncls + RING * slotw + 2 + nt_dp + 2 + nt_dp + 1)
                  * sizeof(float);

    CTCLayer_5669356831169_kernel<<<B, nt, smem>>>(y_true, y_pred, out, T, C, L, nt_dp);
}